// round 5
// baseline (speedup 1.0000x reference)
#include <cuda_runtime.h>
#include <math.h>

#define BB 4
#define NN 256
#define TT 64
#define DD 128
#define DR 32
#define DH 128
#define WF_LD (3*DD+DR)   // 416

// ---------------- device scratch ----------------
__device__ float g_qT  [BB*TT*NN*DH];   // (b,t,n,h)
__device__ float g_kT  [BB*TT*NN*DH];   // (b,t,n,h)
__device__ float g_A   [(size_t)BB*NN*TT*DD];   // (b,n,t,e)
__device__ float g_BpT [(size_t)BB*TT*NN*DD];   // (b,t,j,e) = Bj + Ej
__device__ float g_S   [(size_t)BB*TT*NN*NN];   // (b,t,i,j) scores -> w
__device__ float g_Z2  [(size_t)BB*TT*NN*DD];   // (b,t,i,e)
__device__ float g_P   [BB*NN*TT*DR];   // (b,i,t,r)
__device__ float g_qbr [BB*NN*TT];
__device__ float g_wsum[BB*NN*TT];      // (b,i,t)
__device__ float g_WR  [BB*NN*TT*DR];   // (b,i,t,r)
__device__ float g_Ej  [BB*NN*DD];      // (b,j,e)
__device__ float g_Wcat[4*DH*DD];       // [Wq;Wk;W1;W2]
__device__ float g_WQR [DD*DR];
__device__ float g_brq [DR];
__device__ float g_wqbr[DD];
__device__ float g_c0;

// ---------------- kprep: fold Wq into Wr path ----------------
__global__ void kprep(const float* __restrict__ Wq, const float* __restrict__ bq,
                      const float* __restrict__ Wr, const float* __restrict__ br) {
    int d = threadIdx.x; // 128
    float acc[DR];
    #pragma unroll
    for (int r = 0; r < DR; r++) acc[r] = 0.f;
    float wq_br = 0.f;
    for (int h = 0; h < DH; h++) {
        float a = Wq[h*DD + d];
        wq_br += a * br[h];
        #pragma unroll
        for (int r = 0; r < DR; r++) acc[r] += a * Wr[h*DR + r];
    }
    #pragma unroll
    for (int r = 0; r < DR; r++) g_WQR[d*DR + r] = acc[r];
    g_wqbr[d] = wq_br;
    if (d < DR) {
        float s = 0.f;
        for (int h = 0; h < DH; h++) s += bq[h] * Wr[h*DR + d];
        g_brq[d] = s;
    }
    if (d == 0) {
        float s = 0.f;
        for (int h = 0; h < DH; h++) s += bq[h] * br[h];
        g_c0 = s;
    }
}

// ---------------- kw: build concatenated weights [Wq;Wk;W1;W2] ----------------
__global__ void kw_build(const float* __restrict__ Wq, const float* __restrict__ Wk,
                         const float* __restrict__ Wf) {
    int idx = blockIdx.x*blockDim.x + threadIdx.x;
    if (idx >= 4*DH*DD) return;
    int r = idx / DD, c = idx - r*DD;
    float v;
    if      (r < DH)   v = Wq[r*DD + c];
    else if (r < 2*DH) v = Wk[(r-DH)*DD + c];
    else if (r < 3*DH) v = Wf[(r-2*DH)*WF_LD + c];          // W1
    else               v = Wf[(r-3*DH)*WF_LD + DD + c];     // W2
    g_Wcat[idx] = v;
}

// ---------------- k0: Ej = (sum_t delta_H) @ W4^T ----------------
__global__ __launch_bounds__(DD) void k0_ej(const float* __restrict__ dH,
                                            const float* __restrict__ Wf) {
    int b = blockIdx.x >> 8, j = blockIdx.x & 255;
    __shared__ float dsum[DD];
    int d = threadIdx.x;
    const float* p = dH + (size_t)(b*NN + j)*TT*DD + d;
    float s = 0.f;
    #pragma unroll 8
    for (int t = 0; t < TT; t++) s += p[t*DD];
    dsum[d] = s;
    __syncthreads();
    const float* w4 = Wf + d*WF_LD + 2*DD + DR;   // W4 row e=d
    float acc = 0.f;
    #pragma unroll 8
    for (int dd = 0; dd < DD; dd++) acc += dsum[dd]*w4[dd];
    g_Ej[(b*NN + j)*DD + d] = acc;
}

// ---------------- k1: fused projection GEMM  out = H @ Wcat^T ----------------
// M = B*N*T = 65536, Ncols = 512, K = 128. Tile 128x128, thread 8x8.
__global__ __launch_bounds__(256) void k1_proj(const float* __restrict__ H,
                                               const float* __restrict__ bq,
                                               const float* __restrict__ bk) {
    __shared__ __align__(16) float As[16][132];
    __shared__ __align__(16) float Bs[16][132];
    __shared__ float biasq[DH], biask[DH];
    int tid = threadIdx.x;
    if (tid < DH) { biasq[tid] = bq[tid]; biask[tid] = bk[tid]; }
    const int n0 = blockIdx.x * 128;
    const int m0 = blockIdx.y * 128;
    int tx = tid & 15, ty = tid >> 4;
    float acc[8][8];
    #pragma unroll
    for (int i = 0; i < 8; i++)
        #pragma unroll
        for (int j = 0; j < 8; j++) acc[i][j] = 0.f;

    for (int kc = 0; kc < DD; kc += 16) {
        #pragma unroll
        for (int l = 0; l < 8; l++) {
            int f = l*256 + tid; int m = f >> 4; int kk = f & 15;
            As[kk][m] = H[(size_t)(m0 + m)*DD + kc + kk];
        }
        #pragma unroll
        for (int l = 0; l < 8; l++) {
            int f = l*256 + tid; int n = f >> 4; int kk = f & 15;
            Bs[kk][n] = g_Wcat[(n0 + n)*DD + kc + kk];
        }
        __syncthreads();
        #pragma unroll
        for (int kk = 0; kk < 16; kk++) {
            float4 a0 = *(const float4*)&As[kk][ty*8];
            float4 a1 = *(const float4*)&As[kk][ty*8 + 4];
            float4 b0 = *(const float4*)&Bs[kk][tx*8];
            float4 b1 = *(const float4*)&Bs[kk][tx*8 + 4];
            float a[8] = {a0.x,a0.y,a0.z,a0.w,a1.x,a1.y,a1.z,a1.w};
            float bb[8] = {b0.x,b0.y,b0.z,b0.w,b1.x,b1.y,b1.z,b1.w};
            #pragma unroll
            for (int i = 0; i < 8; i++)
                #pragma unroll
                for (int j = 0; j < 8; j++) acc[i][j] += a[i]*bb[j];
        }
        __syncthreads();
    }
    int seg = blockIdx.x;  // 0:q 1:k 2:A 3:Bp
    int hbase = tx*8;
    #pragma unroll
    for (int i = 0; i < 8; i++) {
        int m = m0 + ty*8 + i;
        int b_ = m >> 14; int nn = (m >> 6) & 255; int t = m & 63;
        if (seg == 0) {
            float* dst = g_qT + ((size_t)((b_*TT + t)*NN + nn))*DH + hbase;
            #pragma unroll
            for (int j = 0; j < 8; j++) dst[j] = acc[i][j] + biasq[hbase + j];
        } else if (seg == 1) {
            float* dst = g_kT + ((size_t)((b_*TT + t)*NN + nn))*DH + hbase;
            #pragma unroll
            for (int j = 0; j < 8; j++) dst[j] = acc[i][j] + biask[hbase + j];
        } else if (seg == 2) {
            float* dst = g_A + (size_t)m*DD + hbase;
            #pragma unroll
            for (int j = 0; j < 8; j++) dst[j] = acc[i][j];
        } else {
            float* dst = g_BpT + ((size_t)((b_*TT + t)*NN + nn))*DD + hbase;
            const float* ej = g_Ej + (size_t)(b_*NN + nn)*DD + hbase;
            #pragma unroll
            for (int j = 0; j < 8; j++) dst[j] = acc[i][j] + ej[j];
        }
    }
}

// ---------------- kp: P = H @ WQR + brq ; qbr = H @ wqbr + c0 ----------------
__global__ __launch_bounds__(256) void kp_P(const float* __restrict__ H) {
    int bi = blockIdx.x;
    __shared__ float Hs[TT][33];
    __shared__ float Ws[32][DR];
    __shared__ float wqbrs[32];
    int tid = threadIdx.x;
    int t = tid >> 2, rg = (tid & 3)*8;
    float acc[8];
    #pragma unroll
    for (int r = 0; r < 8; r++) acc[r] = 0.f;
    float qacc = 0.f;
    const float* Hbase = H + (size_t)bi*TT*DD;
    for (int d0 = 0; d0 < DD; d0 += 32) {
        #pragma unroll
        for (int l = 0; l < 8; l++) {
            int f = l*256 + tid; int t2 = f >> 5, dd = f & 31;
            Hs[t2][dd] = Hbase[t2*DD + d0 + dd];
        }
        #pragma unroll
        for (int l = 0; l < 4; l++) {
            int f = l*256 + tid; int dd = f >> 5, r = f & 31;
            Ws[dd][r] = g_WQR[(d0 + dd)*DR + r];
        }
        if (tid < 32) wqbrs[tid] = g_wqbr[d0 + tid];
        __syncthreads();
        #pragma unroll
        for (int dd = 0; dd < 32; dd++) {
            float a = Hs[t][dd];
            #pragma unroll
            for (int rr = 0; rr < 8; rr++) acc[rr] += a * Ws[dd][rg + rr];
            qacc += a * wqbrs[dd];
        }
        __syncthreads();
    }
    size_t pb = ((size_t)bi*TT + t)*DR + rg;
    #pragma unroll
    for (int rr = 0; rr < 8; rr++) g_P[pb + rr] = acc[rr] + g_brq[rg + rr];
    if (rg == 0) g_qbr[(size_t)bi*TT + t] = qacc + g_c0;
}

// ---------------- k2: scores_qk per (b,t): Q @ K^T ----------------
__global__ __launch_bounds__(256) void k2_qk() {
    int bt = blockIdx.z;
    const float* Q = g_qT + (size_t)bt*NN*DH;
    const float* K = g_kT + (size_t)bt*NN*DH;
    float* C = g_S + (size_t)bt*NN*NN;
    int m0 = blockIdx.y*128, n0 = blockIdx.x*128;
    __shared__ __align__(16) float As[16][132];
    __shared__ __align__(16) float Bs[16][132];
    int tid = threadIdx.x; int tx = tid & 15, ty = tid >> 4;
    float acc[8][8];
    #pragma unroll
    for (int i = 0; i < 8; i++)
        #pragma unroll
        for (int j = 0; j < 8; j++) acc[i][j] = 0.f;
    for (int kc = 0; kc < DH; kc += 16) {
        #pragma unroll
        for (int l = 0; l < 8; l++) {
            int f = l*256 + tid; int m = f >> 4, kk = f & 15;
            As[kk][m] = Q[(size_t)(m0 + m)*DH + kc + kk];
        }
        #pragma unroll
        for (int l = 0; l < 8; l++) {
            int f = l*256 + tid; int n = f >> 4, kk = f & 15;
            Bs[kk][n] = K[(size_t)(n0 + n)*DH + kc + kk];
        }
        __syncthreads();
        #pragma unroll
        for (int kk = 0; kk < 16; kk++) {
            float4 a0 = *(const float4*)&As[kk][ty*8];
            float4 a1 = *(const float4*)&As[kk][ty*8 + 4];
            float4 b0 = *(const float4*)&Bs[kk][tx*8];
            float4 b1 = *(const float4*)&Bs[kk][tx*8 + 4];
            float a[8] = {a0.x,a0.y,a0.z,a0.w,a1.x,a1.y,a1.z,a1.w};
            float bb[8] = {b0.x,b0.y,b0.z,b0.w,b1.x,b1.y,b1.z,b1.w};
            #pragma unroll
            for (int i = 0; i < 8; i++)
                #pragma unroll
                for (int j = 0; j < 8; j++) acc[i][j] += a[i]*bb[j];
        }
        __syncthreads();
    }
    #pragma unroll
    for (int i = 0; i < 8; i++) {
        float* dst = C + (size_t)(m0 + ty*8 + i)*NN + n0 + tx*8;
        #pragma unroll
        for (int j = 0; j < 8; j++) dst[j] = acc[i][j];
    }
}

// ---------------- ksoft: add R-term, softmax over t, mask, wsum ----------------
__global__ __launch_bounds__(256) void ksoft(const float* __restrict__ R) {
    int bi = blockIdx.x; int b = bi >> 8, i = bi & 255;
    int j = threadIdx.x;
    __shared__ float Ps[TT][DR];
    __shared__ float qbrs[TT];
    __shared__ float ws[TT];
    #pragma unroll
    for (int l = 0; l < 8; l++) {
        int f = l*256 + j; int t = f >> 5, r = f & 31;
        Ps[t][r] = g_P[((size_t)bi*TT + t)*DR + r];
    }
    if (j < TT) { qbrs[j] = g_qbr[(size_t)bi*TT + j]; ws[j] = 0.f; }
    __syncthreads();
    float Rr[DR];
    const float* Rp = R + ((size_t)bi*NN + j)*DR;
    #pragma unroll
    for (int r4 = 0; r4 < 8; r4++) {
        float4 v = *(const float4*)(Rp + r4*4);
        Rr[r4*4+0] = v.x; Rr[r4*4+1] = v.y; Rr[r4*4+2] = v.z; Rr[r4*4+3] = v.w;
    }
    float sv[TT];
    const float rs = 0.08838834764831845f;  // 1/sqrt(128)
    size_t sbase = ((size_t)b*TT*NN + i)*NN + j;
    #pragma unroll
    for (int t = 0; t < TT; t++) {
        float qk = g_S[sbase + (size_t)t*NN*NN];
        float rt = 0.f;
        #pragma unroll
        for (int r = 0; r < DR; r++) rt += Ps[t][r]*Rr[r];
        sv[t] = (qk + rt + qbrs[t])*rs;
    }
    float mx = sv[0];
    #pragma unroll
    for (int t = 1; t < TT; t++) mx = fmaxf(mx, sv[t]);
    float sum = 0.f;
    #pragma unroll
    for (int t = 0; t < TT; t++) { sv[t] = __expf(sv[t]-mx); sum += sv[t]; }
    float inv = (j == i) ? 0.f : (1.f/sum);
    int lane = j & 31;
    #pragma unroll
    for (int t = 0; t < TT; t++) {
        float wv = sv[t]*inv;
        g_S[sbase + (size_t)t*NN*NN] = wv;
        float red = wv;
        #pragma unroll
        for (int o = 16; o; o >>= 1) red += __shfl_xor_sync(0xffffffffu, red, o);
        if (lane == 0) atomicAdd(&ws[t], red);
    }
    __syncthreads();
    if (j < TT) g_wsum[(size_t)bi*TT + j] = ws[j];
}

// ---------------- kwr: WR[b,i,t,r] = sum_j w[b,t,i,j] * R[b,i,j,r] ----------------
__global__ __launch_bounds__(256) void kwr(const float* __restrict__ R) {
    int bi = blockIdx.x; int b = bi >> 8, i = bi & 255;
    __shared__ float Rs[32][33];
    __shared__ float wsm[TT][33];
    int tid = threadIdx.x;
    int t = tid >> 2, rg = (tid & 3)*8;
    float acc[8];
    #pragma unroll
    for (int r = 0; r < 8; r++) acc[r] = 0.f;
    for (int j0 = 0; j0 < NN; j0 += 32) {
        #pragma unroll
        for (int l = 0; l < 4; l++) {
            int f = l*256 + tid; int jj = f >> 5, r = f & 31;
            Rs[jj][r] = R[((size_t)bi*NN + j0 + jj)*DR + r];
        }
        #pragma unroll
        for (int l = 0; l < 8; l++) {
            int f = l*256 + tid; int t2 = f >> 5, jj = f & 31;
            wsm[t2][jj] = g_S[((size_t)(b*TT + t2)*NN + i)*NN + j0 + jj];
        }
        __syncthreads();
        #pragma unroll
        for (int jj = 0; jj < 32; jj++) {
            float wv = wsm[t][jj];
            #pragma unroll
            for (int rr = 0; rr < 8; rr++) acc[rr] += wv * Rs[jj][rg + rr];
        }
        __syncthreads();
    }
    size_t ob = ((size_t)bi*TT + t)*DR + rg;
    #pragma unroll
    for (int rr = 0; rr < 8; rr++) g_WR[ob + rr] = acc[rr];
}

// ---------------- k3: z2 per (b,t): w @ (Bj+Ej) ----------------
__global__ __launch_bounds__(256) void k3_z2() {
    int bt = blockIdx.z;
    const float* W = g_S   + (size_t)bt*NN*NN;
    const float* Bp = g_BpT + (size_t)bt*NN*DD;
    float* C = g_Z2 + (size_t)bt*NN*DD;
    int m0 = blockIdx.y*128;
    __shared__ __align__(16) float As[16][132];
    __shared__ __align__(16) float Bs[16][132];
    int tid = threadIdx.x; int tx = tid & 15, ty = tid >> 4;
    float acc[8][8];
    #pragma unroll
    for (int i = 0; i < 8; i++)
        #pragma unroll
        for (int j = 0; j < 8; j++) acc[i][j] = 0.f;
    for (int kc = 0; kc < NN; kc += 16) {
        #pragma unroll
        for (int l = 0; l < 8; l++) {
            int f = l*256 + tid; int m = f >> 4, kk = f & 15;
            As[kk][m] = W[(size_t)(m0 + m)*NN + kc + kk];
        }
        #pragma unroll
        for (int l = 0; l < 8; l++) {
            int f = l*256 + tid; int kk = f >> 7, n = f & 127;
            Bs[kk][n] = Bp[(size_t)(kc + kk)*DD + n];
        }
        __syncthreads();
        #pragma unroll
        for (int kk = 0; kk < 16; kk++) {
            float4 a0 = *(const float4*)&As[kk][ty*8];
            float4 a1 = *(const float4*)&As[kk][ty*8 + 4];
            float4 b0 = *(const float4*)&Bs[kk][tx*8];
            float4 b1 = *(const float4*)&Bs[kk][tx*8 + 4];
            float a[8] = {a0.x,a0.y,a0.z,a0.w,a1.x,a1.y,a1.z,a1.w};
            float bb[8] = {b0.x,b0.y,b0.z,b0.w,b1.x,b1.y,b1.z,b1.w};
            #pragma unroll
            for (int i = 0; i < 8; i++)
                #pragma unroll
                for (int j = 0; j < 8; j++) acc[i][j] += a[i]*bb[j];
        }
        __syncthreads();
    }
    #pragma unroll
    for (int i = 0; i < 8; i++) {
        float* dst = C + (size_t)(m0 + ty*8 + i)*DD + tx*8;
        #pragma unroll
        for (int j = 0; j < 8; j++) dst[j] = acc[i][j];
    }
}

// ---------------- kfin: z assembly + residual + LayerNorm ----------------
__global__ __launch_bounds__(256) void kfin(const float* __restrict__ H,
                                            const float* __restrict__ Wf,
                                            const float* __restrict__ bf,
                                            const float* __restrict__ gamma,
                                            const float* __restrict__ beta,
                                            float* __restrict__ out) {
    int bi = blockIdx.x; int b = bi >> 8, i = bi & 255;
    __shared__ float W3s[DD][33];
    __shared__ float WRs[TT][DR];
    __shared__ float wsums[TT];
    __shared__ float bfs[DD], gs[DD], bts[DD];
    __shared__ float red[8], red2[8];
    int tid = threadIdx.x;
    #pragma unroll
    for (int l = 0; l < 16; l++) {
        int f = l*256 + tid; int e = f >> 5, r = f & 31;
        W3s[e][r] = Wf[e*WF_LD + 2*DD + r];
    }
    #pragma unroll
    for (int l = 0; l < 8; l++) {
        int f = l*256 + tid; int t = f >> 5, r = f & 31;
        WRs[t][r] = g_WR[((size_t)bi*TT + t)*DR + r];
    }
    if (tid < TT) wsums[tid] = g_wsum[(size_t)bi*TT + tid];
    if (tid < DD) { bfs[tid] = bf[tid]; gs[tid] = gamma[tid]; bts[tid] = beta[tid]; }
    __syncthreads();
    int half = tid >> 7; int e = tid & 127; int lane = tid & 31; int w = tid >> 5;
    for (int tt = 0; tt < 32; tt++) {
        int t = tt*2 + half;
        size_t rowH = ((size_t)bi*TT + t)*DD;
        size_t rowZ = ((size_t)(b*TT + t)*NN + i)*DD;
        float v = H[rowH + e] + (g_A[rowH + e] + bfs[e])*wsums[t] + g_Z2[rowZ + e];
        float z3 = 0.f;
        #pragma unroll
        for (int r = 0; r < DR; r++) z3 += WRs[t][r]*W3s[e][r];
        v += z3;
        float s1 = v, s2 = v*v;
        #pragma unroll
        for (int o = 16; o; o >>= 1) {
            s1 += __shfl_xor_sync(0xffffffffu, s1, o);
            s2 += __shfl_xor_sync(0xffffffffu, s2, o);
        }
        if (lane == 0) { red[w] = s1; red2[w] = s2; }
        __syncthreads();
        int wb = half*4;
        float mu = (red[wb] + red[wb+1] + red[wb+2] + red[wb+3]) * (1.f/128.f);
        float ms = (red2[wb] + red2[wb+1] + red2[wb+2] + red2[wb+3]) * (1.f/128.f);
        float var = ms - mu*mu;
        out[rowH + e] = (v - mu)*rsqrtf(var + 1e-5f)*gs[e] + bts[e];
        __syncthreads();
    }
}

// ---------------- launch ----------------
extern "C" void kernel_launch(void* const* d_in, const int* in_sizes, int n_in,
                              void* d_out, int out_size) {
    const float* H      = (const float*)d_in[0];
    const float* R      = (const float*)d_in[1];
    const float* deltaH = (const float*)d_in[2];
    const float* Wq     = (const float*)d_in[3];
    const float* bq     = (const float*)d_in[4];
    const float* Wk     = (const float*)d_in[5];
    const float* bk     = (const float*)d_in[6];
    const float* Wr     = (const float*)d_in[7];
    const float* br     = (const float*)d_in[8];
    const float* Wf     = (const float*)d_in[9];
    const float* bf     = (const float*)d_in[10];
    const float* gamma  = (const float*)d_in[11];
    const float* beta   = (const float*)d_in[12];
    float* out = (float*)d_out;

    kprep<<<1, 128>>>(Wq, bq, Wr, br);
    kw_build<<<256, 256>>>(Wq, Wk, Wf);
    k0_ej<<<BB*NN, DD>>>(deltaH, Wf);
    k1_proj<<<dim3(4, 512), 256>>>(H, bq, bk);
    kp_P<<<BB*NN, 256>>>(H);
    k2_qk<<<dim3(2, 2, BB*TT), 256>>>();
    ksoft<<<BB*NN, 256>>>(R);
    kwr<<<BB*NN, 256>>>(R);
    k3_z2<<<dim3(1, 2, BB*TT), 256>>>();
    kfin<<<BB*NN, 256>>>(H, Wf, bf, gamma, beta, out);
}

// round 7
// speedup vs baseline: 1.2452x; 1.2452x over previous
#include <cuda_runtime.h>
#include <cuda_bf16.h>
#include <math.h>
#include <stdint.h>

#define BB 4
#define NN 256
#define TT 64
#define DD 128
#define DR 32
#define DH 128
#define WF_LD (3*DD+DR)   // 416

// ---------------- device scratch ----------------
__device__ float g_A   [(size_t)BB*NN*TT*DD];   // (b,n,t,e)
__device__ float g_S   [(size_t)BB*TT*NN*NN];   // (b,t,i,j) scores -> w (fp32)
__device__ float g_Z2  [(size_t)BB*TT*NN*DD];   // (b,t,i,e)
__device__ float g_P   [BB*NN*TT*DR];   // (b,i,t,r)
__device__ float g_qbr [BB*NN*TT];
__device__ float g_wsum[BB*NN*TT];      // (b,i,t)
__device__ float g_WR  [BB*NN*TT*DR];   // (b,i,t,r)
__device__ float g_Ej  [BB*NN*DD];      // (b,j,e)
__device__ float g_WQR [DD*DR];
__device__ float g_brq [DR];
__device__ float g_wqbr[DD];
__device__ float g_c0;

// bf16 split operands
__device__ __nv_bfloat16 g_Hh [(size_t)BB*NN*TT*DD];
__device__ __nv_bfloat16 g_Hl [(size_t)BB*NN*TT*DD];
__device__ __nv_bfloat16 g_Wch[4*DH*DD];
__device__ __nv_bfloat16 g_Wcl[4*DH*DD];
__device__ __nv_bfloat16 g_qh [(size_t)BB*TT*NN*DH];
__device__ __nv_bfloat16 g_ql [(size_t)BB*TT*NN*DH];
__device__ __nv_bfloat16 g_kh [(size_t)BB*TT*NN*DH];
__device__ __nv_bfloat16 g_kl [(size_t)BB*TT*NN*DH];
__device__ __nv_bfloat16 g_Bph[(size_t)BB*TT*NN*DD];
__device__ __nv_bfloat16 g_Bpl[(size_t)BB*TT*NN*DD];
__device__ __nv_bfloat16 g_wh [(size_t)BB*TT*NN*NN];
__device__ __nv_bfloat16 g_wl [(size_t)BB*TT*NN*NN];

// ---------------- helpers ----------------
__device__ __forceinline__ void split2(float x, __nv_bfloat16* ph, __nv_bfloat16* pl) {
    __nv_bfloat16 h = __float2bfloat16(x);
    *ph = h;
    *pl = __float2bfloat16(x - __bfloat162float(h));
}

__device__ __forceinline__ uint32_t smem_u32p(const void* p) {
    return (uint32_t)__cvta_generic_to_shared(p);
}

__device__ __forceinline__ void ldsm4(uint32_t& r0, uint32_t& r1, uint32_t& r2, uint32_t& r3, uint32_t a) {
    asm volatile("ldmatrix.sync.aligned.m8n8.x4.shared.b16 {%0,%1,%2,%3}, [%4];"
                 : "=r"(r0), "=r"(r1), "=r"(r2), "=r"(r3) : "r"(a));
}
__device__ __forceinline__ void ldsm4t(uint32_t& r0, uint32_t& r1, uint32_t& r2, uint32_t& r3, uint32_t a) {
    asm volatile("ldmatrix.sync.aligned.m8n8.x4.trans.shared.b16 {%0,%1,%2,%3}, [%4];"
                 : "=r"(r0), "=r"(r1), "=r"(r2), "=r"(r3) : "r"(a));
}
__device__ __forceinline__ void mma16816(float* c, const uint32_t* a, const uint32_t* b) {
    asm volatile("mma.sync.aligned.m16n8k16.row.col.f32.bf16.bf16.f32 "
                 "{%0,%1,%2,%3},{%4,%5,%6,%7},{%8,%9},{%0,%1,%2,%3};"
                 : "+f"(c[0]), "+f"(c[1]), "+f"(c[2]), "+f"(c[3])
                 : "r"(a[0]), "r"(a[1]), "r"(a[2]), "r"(a[3]), "r"(b[0]), "r"(b[1]));
}

// ---------------- kprep: fold Wq into Wr path ----------------
__global__ void kprep(const float* __restrict__ Wq, const float* __restrict__ bq,
                      const float* __restrict__ Wr, const float* __restrict__ br) {
    int d = threadIdx.x; // 128
    float acc[DR];
    #pragma unroll
    for (int r = 0; r < DR; r++) acc[r] = 0.f;
    float wq_br = 0.f;
    for (int h = 0; h < DH; h++) {
        float a = Wq[h*DD + d];
        wq_br += a * br[h];
        #pragma unroll
        for (int r = 0; r < DR; r++) acc[r] += a * Wr[h*DR + r];
    }
    #pragma unroll
    for (int r = 0; r < DR; r++) g_WQR[d*DR + r] = acc[r];
    g_wqbr[d] = wq_br;
    if (d < DR) {
        float s = 0.f;
        for (int h = 0; h < DH; h++) s += bq[h] * Wr[h*DR + d];
        g_brq[d] = s;
    }
    if (d == 0) {
        float s = 0.f;
        for (int h = 0; h < DH; h++) s += bq[h] * br[h];
        g_c0 = s;
    }
}

// ---------------- kw: build concatenated weights [Wq;Wk;W1;W2] as bf16 hi/lo ----------------
__global__ void kw_build(const float* __restrict__ Wq, const float* __restrict__ Wk,
                         const float* __restrict__ Wf) {
    int idx = blockIdx.x*blockDim.x + threadIdx.x;
    if (idx >= 4*DH*DD) return;
    int r = idx / DD, c = idx - r*DD;
    float v;
    if      (r < DH)   v = Wq[r*DD + c];
    else if (r < 2*DH) v = Wk[(r-DH)*DD + c];
    else if (r < 3*DH) v = Wf[(r-2*DH)*WF_LD + c];          // W1
    else               v = Wf[(r-3*DH)*WF_LD + DD + c];     // W2
    split2(v, &g_Wch[idx], &g_Wcl[idx]);
}

// ---------------- kconv_H: H fp32 -> bf16 hi/lo ----------------
__global__ void kconv_H(const float* __restrict__ H) {
    int i = blockIdx.x*blockDim.x + threadIdx.x;
    float x = H[i];
    split2(x, &g_Hh[i], &g_Hl[i]);
}

// ---------------- k0: Ej = (sum_t delta_H) @ W4^T ----------------
__global__ __launch_bounds__(DD) void k0_ej(const float* __restrict__ dH,
                                            const float* __restrict__ Wf) {
    int b = blockIdx.x >> 8, j = blockIdx.x & 255;
    __shared__ float dsum[DD];
    int d = threadIdx.x;
    const float* p = dH + (size_t)(b*NN + j)*TT*DD + d;
    float s = 0.f;
    #pragma unroll 8
    for (int t = 0; t < TT; t++) s += p[t*DD];
    dsum[d] = s;
    __syncthreads();
    const float* w4 = Wf + d*WF_LD + 2*DD + DR;   // W4 row e=d
    float acc = 0.f;
    #pragma unroll 8
    for (int dd = 0; dd < DD; dd++) acc += dsum[dd]*w4[dd];
    g_Ej[(b*NN + j)*DD + d] = acc;
}

// ---------------- k1m: fused projection GEMM (tensor cores, bf16 split) ----------------
// out = H @ Wcat^T : M=65536, Ncol=512, K=128. CTA 128x128, 8 warps of 64x32.
__global__ __launch_bounds__(256) void k1m(const float* __restrict__ bq,
                                           const float* __restrict__ bk) {
    __shared__ __align__(16) __nv_bfloat16 As[128][72];
    __shared__ __align__(16) __nv_bfloat16 Bs[128][72];
    __shared__ float biasq[DH], biask[DH];
    int tid = threadIdx.x, lane = tid & 31, w = tid >> 5;
    int wm = w & 1, wn = w >> 1;
    if (tid < DH) { biasq[tid] = bq[tid]; biask[tid] = bk[tid]; }
    const int n0 = blockIdx.x * 128;
    const int m0 = blockIdx.y * 128;
    float acc[4][4][4];
    #pragma unroll
    for (int i = 0; i < 4; i++)
        #pragma unroll
        for (int j = 0; j < 4; j++)
            #pragma unroll
            for (int r = 0; r < 4; r++) acc[i][j][r] = 0.f;
    uint32_t asb = smem_u32p(&As[0][0]);
    uint32_t bsb = smem_u32p(&Bs[0][0]);
    const uint32_t* Ah32 = (const uint32_t*)g_Hh;
    const uint32_t* Al32 = (const uint32_t*)g_Hl;
    const uint32_t* Bh32 = (const uint32_t*)g_Wch;
    const uint32_t* Bl32 = (const uint32_t*)g_Wcl;

    #pragma unroll 1
    for (int p = 0; p < 3; p++) {
        const uint32_t* Asrc = (p == 1) ? Al32 : Ah32;
        const uint32_t* Bsrc = (p == 2) ? Bl32 : Bh32;
        #pragma unroll 1
        for (int kc = 0; kc < 2; kc++) {    // two 64-wide (32 u32) k-chunks
            #pragma unroll
            for (int l = 0; l < 16; l++) {
                int f = l*256 + tid; int r = f >> 5, cu = f & 31;
                ((uint32_t*)As)[r*36 + cu] = Asrc[(size_t)(m0 + r)*64 + kc*32 + cu];
            }
            #pragma unroll
            for (int l = 0; l < 16; l++) {
                int f = l*256 + tid; int r = f >> 5, cu = f & 31;
                ((uint32_t*)Bs)[r*36 + cu] = Bsrc[(size_t)(n0 + r)*64 + kc*32 + cu];
            }
            __syncthreads();
            #pragma unroll
            for (int ki = 0; ki < 4; ki++) {
                uint32_t a[4][4], b[4][2];
                #pragma unroll
                for (int mf = 0; mf < 4; mf++)
                    ldsm4(a[mf][0], a[mf][1], a[mf][2], a[mf][3],
                          asb + ((wm*64 + mf*16 + (lane & 15))*72 + ki*16 + (lane >> 4)*8)*2);
                #pragma unroll
                for (int g = 0; g < 2; g++) {
                    uint32_t r0, r1, r2, r3;
                    ldsm4(r0, r1, r2, r3,
                          bsb + ((wn*32 + g*16 + (lane & 15))*72 + ki*16 + (lane >> 4)*8)*2);
                    b[g*2][0] = r0; b[g*2][1] = r2; b[g*2+1][0] = r1; b[g*2+1][1] = r3;
                }
                #pragma unroll
                for (int mf = 0; mf < 4; mf++)
                    #pragma unroll
                    for (int nf = 0; nf < 4; nf++) mma16816(acc[mf][nf], a[mf], b[nf]);
            }
            __syncthreads();
        }
    }
    // epilogue
    int seg = blockIdx.x;  // 0:q 1:k 2:A 3:Bp
    #pragma unroll
    for (int mf = 0; mf < 4; mf++)
        #pragma unroll
        for (int nf = 0; nf < 4; nf++)
            #pragma unroll
            for (int r = 0; r < 4; r++) {
                int m = m0 + wm*64 + mf*16 + (lane >> 2) + ((r >> 1) << 3);
                int nl = wn*32 + nf*8 + ((lane & 3) << 1) + (r & 1);
                float v = acc[mf][nf][r];
                int b_ = m >> 14, nn = (m >> 6) & 255, t = m & 63;
                size_t base = (size_t)((b_*TT + t)*NN + nn);
                if (seg == 0) {
                    size_t d = base*DH + nl;
                    split2(v + biasq[nl], g_qh + d, g_ql + d);
                } else if (seg == 1) {
                    size_t d = base*DH + nl;
                    split2(v + biask[nl], g_kh + d, g_kl + d);
                } else if (seg == 2) {
                    g_A[(size_t)m*DD + nl] = v;
                } else {
                    float bpv = v + g_Ej[(size_t)(b_*NN + nn)*DD + nl];
                    size_t d = base*DD + nl;
                    split2(bpv, g_Bph + d, g_Bpl + d);
                }
            }
}

// ---------------- k2m: scores per (b,t): Q @ K^T (tensor cores) ----------------
__global__ __launch_bounds__(256) void k2m() {
    __shared__ __align__(16) __nv_bfloat16 As[128][72];
    __shared__ __align__(16) __nv_bfloat16 Bs[128][72];
    int tid = threadIdx.x, lane = tid & 31, w = tid >> 5;
    int wm = w & 1, wn = w >> 1;
    int bt = blockIdx.z;
    const int n0 = blockIdx.x * 128;
    const int m0 = blockIdx.y * 128;
    float acc[4][4][4];
    #pragma unroll
    for (int i = 0; i < 4; i++)
        #pragma unroll
        for (int j = 0; j < 4; j++)
            #pragma unroll
            for (int r = 0; r < 4; r++) acc[i][j][r] = 0.f;
    uint32_t asb = smem_u32p(&As[0][0]);
    uint32_t bsb = smem_u32p(&Bs[0][0]);
    const uint32_t* qh32 = (const uint32_t*)g_qh + (size_t)bt*NN*64;
    const uint32_t* ql32 = (const uint32_t*)g_ql + (size_t)bt*NN*64;
    const uint32_t* kh32 = (const uint32_t*)g_kh + (size_t)bt*NN*64;
    const uint32_t* kl32 = (const uint32_t*)g_kl + (size_t)bt*NN*64;

    #pragma unroll 1
    for (int p = 0; p < 3; p++) {
        const uint32_t* Asrc = (p == 1) ? ql32 : qh32;
        const uint32_t* Bsrc = (p == 2) ? kl32 : kh32;
        #pragma unroll 1
        for (int kc = 0; kc < 2; kc++) {
            #pragma unroll
            for (int l = 0; l < 16; l++) {
                int f = l*256 + tid; int r = f >> 5, cu = f & 31;
                ((uint32_t*)As)[r*36 + cu] = Asrc[(size_t)(m0 + r)*64 + kc*32 + cu];
            }
            #pragma unroll
            for (int l = 0; l < 16; l++) {
                int f = l*256 + tid; int r = f >> 5, cu = f & 31;
                ((uint32_t*)Bs)[r*36 + cu] = Bsrc[(size_t)(n0 + r)*64 + kc*32 + cu];
            }
            __syncthreads();
            #pragma unroll
            for (int ki = 0; ki < 4; ki++) {
                uint32_t a[4][4], b[4][2];
                #pragma unroll
                for (int mf = 0; mf < 4; mf++)
                    ldsm4(a[mf][0], a[mf][1], a[mf][2], a[mf][3],
                          asb + ((wm*64 + mf*16 + (lane & 15))*72 + ki*16 + (lane >> 4)*8)*2);
                #pragma unroll
                for (int g = 0; g < 2; g++) {
                    uint32_t r0, r1, r2, r3;
                    ldsm4(r0, r1, r2, r3,
                          bsb + ((wn*32 + g*16 + (lane & 15))*72 + ki*16 + (lane >> 4)*8)*2);
                    b[g*2][0] = r0; b[g*2][1] = r2; b[g*2+1][0] = r1; b[g*2+1][1] = r3;
                }
                #pragma unroll
                for (int mf = 0; mf < 4; mf++)
                    #pragma unroll
                    for (int nf = 0; nf < 4; nf++) mma16816(acc[mf][nf], a[mf], b[nf]);
            }
            __syncthreads();
        }
    }
    float* C = g_S + (size_t)bt*NN*NN;
    #pragma unroll
    for (int mf = 0; mf < 4; mf++)
        #pragma unroll
        for (int nf = 0; nf < 4; nf++) {
            int m = m0 + wm*64 + mf*16 + (lane >> 2);
            int n = n0 + wn*32 + nf*8 + ((lane & 3) << 1);
            float2 v0 = make_float2(acc[mf][nf][0], acc[mf][nf][1]);
            float2 v1 = make_float2(acc[mf][nf][2], acc[mf][nf][3]);
            *(float2*)&C[(size_t)m*NN + n] = v0;
            *(float2*)&C[(size_t)(m + 8)*NN + n] = v1;
        }
}

// ---------------- ksoft: add R-term, softmax over t, mask, wsum, write w (fp32 + bf16 split) ----------------
__global__ __launch_bounds__(256) void ksoft(const float* __restrict__ R) {
    int bi = blockIdx.x; int b = bi >> 8, i = bi & 255;
    int j = threadIdx.x;
    __shared__ float Ps[TT][DR];
    __shared__ float qbrs[TT];
    __shared__ float ws[TT];
    #pragma unroll
    for (int l = 0; l < 8; l++) {
        int f = l*256 + j; int t = f >> 5, r = f & 31;
        Ps[t][r] = g_P[((size_t)bi*TT + t)*DR + r];
    }
    if (j < TT) { qbrs[j] = g_qbr[(size_t)bi*TT + j]; ws[j] = 0.f; }
    __syncthreads();
    float Rr[DR];
    const float* Rp = R + ((size_t)bi*NN + j)*DR;
    #pragma unroll
    for (int r4 = 0; r4 < 8; r4++) {
        float4 v = *(const float4*)(Rp + r4*4);
        Rr[r4*4+0] = v.x; Rr[r4*4+1] = v.y; Rr[r4*4+2] = v.z; Rr[r4*4+3] = v.w;
    }
    float sv[TT];
    const float rs = 0.08838834764831845f;  // 1/sqrt(128)
    size_t sbase = ((size_t)b*TT*NN + i)*NN + j;
    #pragma unroll
    for (int t = 0; t < TT; t++) {
        float qk = g_S[sbase + (size_t)t*NN*NN];
        float rt = 0.f;
        #pragma unroll
        for (int r = 0; r < DR; r++) rt += Ps[t][r]*Rr[r];
        sv[t] = (qk + rt + qbrs[t])*rs;
    }
    float mx = sv[0];
    #pragma unroll
    for (int t = 1; t < TT; t++) mx = fmaxf(mx, sv[t]);
    float sum = 0.f;
    #pragma unroll
    for (int t = 0; t < TT; t++) { sv[t] = __expf(sv[t]-mx); sum += sv[t]; }
    float inv = (j == i) ? 0.f : (1.f/sum);
    int lane = j & 31;
    #pragma unroll
    for (int t = 0; t < TT; t++) {
        float wv = sv[t]*inv;
        size_t idx = sbase + (size_t)t*NN*NN;
        g_S[idx] = wv;
        split2(wv, g_wh + idx, g_wl + idx);
        float red = wv;
        #pragma unroll
        for (int o = 16; o; o >>= 1) red += __shfl_xor_sync(0xffffffffu, red, o);
        if (lane == 0) atomicAdd(&ws[t], red);
    }
    __syncthreads();
    if (j < TT) g_wsum[(size_t)bi*TT + j] = ws[j];
}

// ---------------- kp: P = H @ WQR + brq ; qbr = H @ wqbr + c0 ----------------
__global__ __launch_bounds__(256) void kp_P(const float* __restrict__ H) {
    int bi = blockIdx.x;
    __shared__ float Hs[TT][33];
    __shared__ float Ws[32][DR];
    __shared__ float wqbrs[32];
    int tid = threadIdx.x;
    int t = tid >> 2, rg = (tid & 3)*8;
    float acc[8];
    #pragma unroll
    for (int r = 0; r < 8; r++) acc[r] = 0.f;
    float qacc = 0.f;
    const float* Hbase = H + (size_t)bi*TT*DD;
    for (int d0 = 0; d0 < DD; d0 += 32) {
        #pragma unroll
        for (int l = 0; l < 8; l++) {
            int f = l*256 + tid; int t2 = f >> 5, dd = f & 31;
            Hs[t2][dd] = Hbase[t2*DD + d0 + dd];
        }
        #pragma unroll
        for (int l = 0; l < 4; l++) {
            int f = l*256 + tid; int dd = f >> 5, r = f & 31;
            Ws[dd][r] = g_WQR[(d0 + dd)*DR + r];
        }
        if (tid < 32) wqbrs[tid] = g_wqbr[d0 + tid];
        __syncthreads();
        #pragma unroll
        for (int dd = 0; dd < 32; dd++) {
            float a = Hs[t][dd];
            #pragma unroll
            for (int rr = 0; rr < 8; rr++) acc[rr] += a * Ws[dd][rg + rr];
            qacc += a * wqbrs[dd];
        }
        __syncthreads();
    }
    size_t pb = ((size_t)bi*TT + t)*DR + rg;
    #pragma unroll
    for (int rr = 0; rr < 8; rr++) g_P[pb + rr] = acc[rr] + g_brq[rg + rr];
    if (rg == 0) g_qbr[(size_t)bi*TT + t] = qacc + g_c0;
}

// ---------------- kwr: WR[b,i,t,r] = sum_j w[b,t,i,j] * R[b,i,j,r] ----------------
__global__ __launch_bounds__(256) void kwr(const float* __restrict__ R) {
    int bi = blockIdx.x; int b = bi >> 8, i = bi & 255;
    __shared__ float Rs[32][33];
    __shared__ float wsm[TT][33];
    int tid = threadIdx.x;
    int t = tid >> 2, rg = (tid & 3)*8;
    float acc[8];
    #pragma unroll
    for (int r = 0; r < 8; r++) acc[r] = 0.f;
    for (int j0 = 0; j0 < NN; j0 += 32) {
        #pragma unroll
        for (int l = 0; l < 4; l++) {
            int f = l*256 + tid; int jj = f >> 5, r = f & 31;
            Rs[jj][r] = R[((size_t)bi*NN + j0 + jj)*DR + r];
        }
        #pragma unroll
        for (int l = 0; l < 8; l++) {
            int f = l*256 + tid; int t2 = f >> 5, jj = f & 31;
            wsm[t2][jj] = g_S[((size_t)(b*TT + t2)*NN + i)*NN + j0 + jj];
        }
        __syncthreads();
        #pragma unroll
        for (int jj = 0; jj < 32; jj++) {
            float wv = wsm[t][jj];
            #pragma unroll
            for (int rr = 0; rr < 8; rr++) acc[rr] += wv * Rs[jj][rg + rr];
        }
        __syncthreads();
    }
    size_t ob = ((size_t)bi*TT + t)*DR + rg;
    #pragma unroll
    for (int rr = 0; rr < 8; rr++) g_WR[ob + rr] = acc[rr];
}

// ---------------- k3m: z2 per (b,t): w @ Bp (tensor cores; B loaded with trans) ----------------
__global__ __launch_bounds__(256) void k3m() {
    __shared__ __align__(16) __nv_bfloat16 As[128][72];   // w tile: 128 i x 64 j
    __shared__ __align__(16) __nv_bfloat16 Bs[64][136];   // Bp tile: 64 j x 128 e
    int tid = threadIdx.x, lane = tid & 31, w = tid >> 5;
    int wm = w & 1, wn = w >> 1;
    int bt = blockIdx.z;
    const int m0 = blockIdx.y * 128;
    float acc[4][4][4];
    #pragma unroll
    for (int i = 0; i < 4; i++)
        #pragma unroll
        for (int j = 0; j < 4; j++)
            #pragma unroll
            for (int r = 0; r < 4; r++) acc[i][j][r] = 0.f;
    uint32_t asb = smem_u32p(&As[0][0]);
    uint32_t bsb = smem_u32p(&Bs[0][0]);
    const uint32_t* wh32  = (const uint32_t*)g_wh  + (size_t)bt*NN*(NN/2);
    const uint32_t* wl32  = (const uint32_t*)g_wl  + (size_t)bt*NN*(NN/2);
    const uint32_t* bph32 = (const uint32_t*)g_Bph + (size_t)bt*NN*(DD/2);
    const uint32_t* bpl32 = (const uint32_t*)g_Bpl + (size_t)bt*NN*(DD/2);

    #pragma unroll 1
    for (int p = 0; p < 3; p++) {
        const uint32_t* Asrc = (p == 1) ? wl32  : wh32;
        const uint32_t* Bsrc = (p == 2) ? bpl32 : bph32;
        #pragma unroll 1
        for (int kc = 0; kc < 4; kc++) {   // K=256 in 64-wide chunks
            #pragma unroll
            for (int l = 0; l < 16; l++) {
                int f = l*256 + tid; int r = f >> 5, cu = f & 31;
                ((uint32_t*)As)[r*36 + cu] = Asrc[(size_t)(m0 + r)*128 + kc*32 + cu];
            }
            #pragma unroll
            for (int l = 0; l < 16; l++) {
                int f = l*256 + tid; int r = f >> 6, cu = f & 63;
                ((uint32_t*)Bs)[r*68 + cu] = Bsrc[(size_t)(kc*64 + r)*64 + cu];
            }
            __syncthreads();
            #pragma unroll
            for (int ki = 0; ki < 4; ki++) {
                uint32_t a[4][4], b[4][2];
                #pragma unroll
                for (int mf = 0; mf < 4; mf++)
                    ldsm4(a[mf][0], a[mf][1], a[mf][2], a[mf][3],
                          asb + ((wm*64 + mf*16 + (lane & 15))*72 + ki*16 + (lane >> 4)*8)*2);
                #pragma unroll
                for (int g = 0; g < 2; g++) {
                    uint32_t r0, r1, r2, r3;
                    ldsm4t(r0, r1, r2, r3,
                           bsb + ((ki*16 + (lane & 15))*136 + wn*32 + g*16 + (lane >> 4)*8)*2);
                    b[g*2][0] = r0; b[g*2][1] = r1; b[g*2+1][0] = r2; b[g*2+1][1] = r3;
                }
                #pragma unroll
                for (int mf = 0; mf < 4; mf++)
                    #pragma unroll
                    for (int nf = 0; nf < 4; nf++) mma16816(acc[mf][nf], a[mf], b[nf]);
            }
            __syncthreads();
        }
    }
    float* C = g_Z2 + (size_t)bt*NN*DD;
    #pragma unroll
    for (int mf = 0; mf < 4; mf++)
        #pragma unroll
        for (int nf = 0; nf < 4; nf++) {
            int m = m0 + wm*64 + mf*16 + (lane >> 2);
            int n = wn*32 + nf*8 + ((lane & 3) << 1);
            float2 v0 = make_float2(acc[mf][nf][0], acc[mf][nf][1]);
            float2 v1 = make_float2(acc[mf][nf][2], acc[mf][nf][3]);
            *(float2*)&C[(size_t)m*DD + n] = v0;
            *(float2*)&C[(size_t)(m + 8)*DD + n] = v1;
        }
}

// ---------------- kfin: z assembly + residual + LayerNorm ----------------
__global__ __launch_bounds__(256) void kfin(const float* __restrict__ H,
                                            const float* __restrict__ Wf,
                                            const float* __restrict__ bf,
                                            const float* __restrict__ gamma,
                                            const float* __restrict__ beta,
                                            float* __restrict__ out) {
    int bi = blockIdx.x; int b = bi >> 8, i = bi & 255;
    __shared__ float W3s[DD][33];
    __shared__ float WRs[TT][DR];
    __shared__ float wsums[TT];
    __shared__ float bfs[DD], gs[DD], bts[DD];
    __shared__ float red[8], red2[8];
    int tid = threadIdx.x;
    #pragma unroll
    for (int l = 0; l < 16; l++) {
        int f = l*256 + tid; int e = f >> 5, r = f & 31;
        W3s[e][r] = Wf[e*WF_LD + 2*DD + r];
    }
    #pragma unroll
    for (int l = 0; l < 8; l++) {
        int f = l*256 + tid; int t = f >> 5, r = f & 31;
        WRs[t][r] = g_WR[((size_t)bi*TT + t)*DR + r];
    }
    if (tid < TT) wsums[tid] = g_wsum[(size_t)bi*TT + tid];
    if (tid < DD) { bfs[tid] = bf[tid]; gs[tid] = gamma[tid]; bts[tid] = beta[tid]; }
    __syncthreads();
    int half = tid >> 7; int e = tid & 127; int lane = tid & 31; int w = tid >> 5;
    for (int tt = 0; tt < 32; tt++) {
        int t = tt*2 + half;
        size_t rowH = ((size_t)bi*TT + t)*DD;
        size_t rowZ = ((size_t)(b*TT + t)*NN + i)*DD;
        float v = H[rowH + e] + (g_A[rowH + e] + bfs[e])*wsums[t] + g_Z2[rowZ + e];
        float z3 = 0.f;
        #pragma unroll
        for (int r = 0; r < DR; r++) z3 += WRs[t][r]*W3s[e][r];
        v += z3;
        float s1 = v, s2 = v*v;
        #pragma unroll
        for (int o = 16; o; o >>= 1) {
            s1 += __shfl_xor_sync(0xffffffffu, s1, o);
            s2 += __shfl_xor_sync(0xffffffffu, s2, o);
        }
        if (lane == 0) { red[w] = s1; red2[w] = s2; }
        __syncthreads();
        int wb = half*4;
        float mu = (red[wb] + red[wb+1] + red[wb+2] + red[wb+3]) * (1.f/128.f);
        float ms = (red2[wb] + red2[wb+1] + red2[wb+2] + red2[wb+3]) * (1.f/128.f);
        float var = ms - mu*mu;
        out[rowH + e] = (v - mu)*rsqrtf(var + 1e-5f)*gs[e] + bts[e];
        __syncthreads();
    }
}

// ---------------- launch ----------------
extern "C" void kernel_launch(void* const* d_in, const int* in_sizes, int n_in,
                              void* d_out, int out_size) {
    const float* H      = (const float*)d_in[0];
    const float* R      = (const float*)d_in[1];
    const float* deltaH = (const float*)d_in[2];
    const float* Wq     = (const float*)d_in[3];
    const float* bq     = (const float*)d_in[4];
    const float* Wk     = (const float*)d_in[5];
    const float* bk     = (const float*)d_in[6];
    const float* Wr     = (const float*)d_in[7];
    const float* br     = (const float*)d_in[8];
    const float* Wf     = (const float*)d_in[9];
    const float* bf     = (const float*)d_in[10];
    const float* gamma  = (const float*)d_in[11];
    const float* beta   = (const float*)d_in[12];
    float* out = (float*)d_out;

    kprep<<<1, 128>>>(Wq, bq, Wr, br);
    kw_build<<<256, 256>>>(Wq, Wk, Wf);
    kconv_H<<<(BB*NN*TT*DD)/256, 256>>>(H);
    k0_ej<<<BB*NN, DD>>>(deltaH, Wf);
    k1m<<<dim3(4, 512), 256>>>(bq, bk);
    kp_P<<<BB*NN, 256>>>(H);
    k2m<<<dim3(2, 2, BB*TT), 256>>>();
    ksoft<<<BB*NN, 256>>>(R);
    kwr<<<BB*NN, 256>>>(R);
    k3m<<<dim3(1, 2, BB*TT), 256>>>();
    kfin<<<BB*NN, 256>>>(H, Wf, bf, gamma, beta, out);
}